// round 2
// baseline (speedup 1.0000x reference)
#include <cuda_runtime.h>
#include <cstdint>
#include <cstddef>

// ---------------- problem constants ----------------
#define BB   16
#define NNq  1024
#define DD   768
#define HH   12
#define HDD  64
#define PP   16
#define FFF  3072
#define MTOK (BB*NNq)     // 16384
#define LL   (PP+NNq)     // 1040
#define BHh  (BB*HH)      // 192

// ---------------- scratch (device globals; no allocation) ----------------
__device__ float g_h [MTOK*DD];        // LN output (h1 then h2)      50 MB
__device__ float g_q [BHh*NNq*HDD];    // [b,h,t,hd]                  48 MB
__device__ float g_k [BHh*LL*HDD];     // [b,h,P+t,hd]                51 MB
__device__ float g_vt[BHh*HDD*LL];     // [b,h,hd,P+t] (V transposed) 51 MB
__device__ float g_o [MTOK*DD];        // attn out [b,t, h*64+hd]     50 MB
__device__ float g_x1[MTOK*DD];        // residual 1                  50 MB
__device__ float g_m [MTOK*FFF];       // MLP hidden                 201 MB

// buffer selectors (0 = use passed pointer)
template<int SEL>
__device__ __forceinline__ float* buf_ptr(const void* arg) {
    if (SEL == 1) return g_h;
    if (SEL == 2) return g_o;
    if (SEL == 3) return g_x1;
    if (SEL == 4) return g_m;
    return (float*)arg;
}

// ---------------- helpers ----------------
__device__ __forceinline__ uint32_t f2tf32(float x) {
    uint32_t r;
    asm("cvt.rna.tf32.f32 %0, %1;" : "=r"(r) : "f"(x));
    return r;
}

__device__ __forceinline__ void mma_tf32(float c[4], const uint32_t a[4], const uint32_t b[2]) {
    asm volatile(
        "mma.sync.aligned.m16n8k8.row.col.f32.tf32.tf32.f32 "
        "{%0,%1,%2,%3},{%4,%5,%6,%7},{%8,%9},{%0,%1,%2,%3};\n"
        : "+f"(c[0]), "+f"(c[1]), "+f"(c[2]), "+f"(c[3])
        : "r"(a[0]), "r"(a[1]), "r"(a[2]), "r"(a[3]), "r"(b[0]), "r"(b[1]));
}

// ---------------- epilogues ----------------
// 0: QKV scatter (+bias) into g_q / g_k / g_vt
// 3: +bias +res -> out (ldc = DD)
// 4: +bias, QuickGELU -> out (ldc = FFF)
template<int EPI>
__device__ __forceinline__ void do_epi(int r, int c, float v,
                                       const float* __restrict__ bias,
                                       const float* __restrict__ res,
                                       float* __restrict__ out)
{
    if (EPI == 0) {
        v += bias[c];
        int which = c / DD;
        int d = c - which * DD;
        int h = d >> 6, hd = d & 63;
        int b = r >> 10, t = r & 1023;
        int bh = b * HH + h;
        if (which == 0)      g_q [(((size_t)bh << 10) + t) * HDD + hd] = v;
        else if (which == 1) g_k [((size_t)bh * LL + PP + t) * HDD + hd] = v;
        else                 g_vt[((size_t)bh * HDD + hd) * LL + PP + t] = v;
    } else if (EPI == 3) {
        size_t o = (size_t)r * DD + c;
        out[o] = v + bias[c] + res[o];
    } else { // 4
        v += bias[c];
        out[(size_t)r * FFF + c] = v / (1.f + __expf(-1.702f * v));
    }
}

// ---------------- generic NT GEMM (C = A[M,K] * B[N,K]^T), tf32 mma ----------------
// BM=128, BK=32, 256 threads = 8 warps as 4(m) x 2(n); warp tile 32 x (BN/2).
template<int BN, int EPI, int ASEL, int RSEL, int OSEL>
__global__ __launch_bounds__(256)
void gemm_nt(const float* __restrict__ Aarg, int lda,
             const float* __restrict__ B, int ldb,
             int Ntot, int K,
             const float* __restrict__ bias,
             const float* __restrict__ resarg,
             float* __restrict__ outarg)
{
    constexpr int BM = 128, BK = 32;
    constexpr int NT = BN / 16;            // n8 sub-tiles per warp
    __shared__ uint32_t As[BM * 36];
    __shared__ uint32_t Bs[BN * 36];

    const float* A   = buf_ptr<ASEL>(Aarg);
    const float* res = buf_ptr<RSEL>(resarg);
    float*       out = buf_ptr<OSEL>(outarg);

    const int tid  = threadIdx.x;
    const int lane = tid & 31, wid = tid >> 5;
    const int warpM = wid >> 1, warpN = wid & 1;
    const int g  = lane >> 2, tg = lane & 3;
    const int m0 = blockIdx.y * BM;
    const int n0 = blockIdx.x * BN;

    float acc[2][NT][4];
    #pragma unroll
    for (int mt = 0; mt < 2; mt++)
        #pragma unroll
        for (int nt = 0; nt < NT; nt++)
            #pragma unroll
            for (int i = 0; i < 4; i++) acc[mt][nt][i] = 0.f;

    for (int k0 = 0; k0 < K; k0 += BK) {
        #pragma unroll
        for (int i = 0; i < 4; i++) {
            int idx = tid + i * 256;
            int row = idx >> 3, c4 = (idx & 7) * 4;
            float4 v = *(const float4*)(A + (size_t)(m0 + row) * lda + k0 + c4);
            uint32_t* d = &As[row * 36 + c4];
            d[0] = f2tf32(v.x); d[1] = f2tf32(v.y); d[2] = f2tf32(v.z); d[3] = f2tf32(v.w);
        }
        #pragma unroll
        for (int i = 0; i < BN / 32; i++) {
            int idx = tid + i * 256;
            int row = idx >> 3, c4 = (idx & 7) * 4;
            float4 v = make_float4(0.f, 0.f, 0.f, 0.f);
            if (n0 + row < Ntot)
                v = *(const float4*)(B + (size_t)(n0 + row) * ldb + k0 + c4);
            uint32_t* d = &Bs[row * 36 + c4];
            d[0] = f2tf32(v.x); d[1] = f2tf32(v.y); d[2] = f2tf32(v.z); d[3] = f2tf32(v.w);
        }
        __syncthreads();

        #pragma unroll
        for (int ks = 0; ks < 4; ks++) {
            const int kk = ks * 8;
            uint32_t a[2][4];
            uint32_t b[NT][2];
            #pragma unroll
            for (int mt = 0; mt < 2; mt++) {
                int rb = warpM * 32 + mt * 16 + g;
                a[mt][0] = As[rb * 36 + kk + tg];
                a[mt][1] = As[(rb + 8) * 36 + kk + tg];
                a[mt][2] = As[rb * 36 + kk + tg + 4];
                a[mt][3] = As[(rb + 8) * 36 + kk + tg + 4];
            }
            #pragma unroll
            for (int nt = 0; nt < NT; nt++) {
                int cb = warpN * (BN / 2) + nt * 8 + g;
                b[nt][0] = Bs[cb * 36 + kk + tg];
                b[nt][1] = Bs[cb * 36 + kk + tg + 4];
            }
            #pragma unroll
            for (int mt = 0; mt < 2; mt++)
                #pragma unroll
                for (int nt = 0; nt < NT; nt++)
                    mma_tf32(acc[mt][nt], a[mt], b[nt]);
        }
        __syncthreads();
    }

    #pragma unroll
    for (int mt = 0; mt < 2; mt++) {
        #pragma unroll
        for (int nt = 0; nt < NT; nt++) {
            int r0 = m0 + warpM * 32 + mt * 16 + g;
            int c0 = n0 + warpN * (BN / 2) + nt * 8 + tg * 2;
            #pragma unroll
            for (int i = 0; i < 4; i++) {
                int r = r0 + (i >> 1) * 8;
                int c = c0 + (i & 1);
                if (c < Ntot) do_epi<EPI>(r, c, acc[mt][nt][i], bias, res, out);
            }
        }
    }
}

// ---------------- fused flash attention ----------------
// grid (8, 192): x = 128-query tile, y = b*H+h. 8 warps, 16 q-rows each.
__global__ __launch_bounds__(256)
void flash_kernel()
{
    __shared__ uint32_t Ks[64 * 68];   // [key][hd] tf32
    __shared__ uint32_t Vs[64 * 68];   // [hd][key] tf32 (V^T)

    const int tid = threadIdx.x, lane = tid & 31, wid = tid >> 5;
    const int g = lane >> 2, tg = lane & 3;
    const int m0 = blockIdx.x * 128;
    const int bh = blockIdx.y;
    const int b = bh / HH, h = bh - b * HH;
    const int wb = wid * 16;

    // Q fragments straight from gmem (held for whole kernel)
    uint32_t qf[8][4];
    {
        const float* Q1 = g_q + ((size_t)bh * NNq + m0 + wb + g) * HDD;
        const float* Q2 = Q1 + 8 * HDD;
        #pragma unroll
        for (int kt = 0; kt < 8; kt++) {
            qf[kt][0] = f2tf32(Q1[kt * 8 + tg]);
            qf[kt][1] = f2tf32(Q2[kt * 8 + tg]);
            qf[kt][2] = f2tf32(Q1[kt * 8 + tg + 4]);
            qf[kt][3] = f2tf32(Q2[kt * 8 + tg + 4]);
        }
    }

    float m1 = -1e30f, m2 = -1e30f, l1 = 0.f, l2 = 0.f;
    float oacc[8][4];
    #pragma unroll
    for (int nt = 0; nt < 8; nt++)
        #pragma unroll
        for (int i = 0; i < 4; i++) oacc[nt][i] = 0.f;

    for (int t = 0; t < 17; t++) {          // ceil(1040/64)
        const int kb = t * 64;
        __syncthreads();
        // load K tile [key][hd]
        #pragma unroll
        for (int i = 0; i < 4; i++) {
            int idx = tid + i * 256;
            int row = idx >> 4, c4 = (idx & 15) * 4;
            float4 v = make_float4(0.f, 0.f, 0.f, 0.f);
            if (kb + row < LL)
                v = *(const float4*)(g_k + ((size_t)bh * LL + kb + row) * HDD + c4);
            uint32_t* d = &Ks[row * 68 + c4];
            d[0] = f2tf32(v.x); d[1] = f2tf32(v.y); d[2] = f2tf32(v.z); d[3] = f2tf32(v.w);
        }
        // load V^T tile [hd][key]
        #pragma unroll
        for (int i = 0; i < 4; i++) {
            int idx = tid + i * 256;
            int row = idx >> 4, c4 = (idx & 15) * 4;
            float4 v = make_float4(0.f, 0.f, 0.f, 0.f);
            if (kb + c4 + 4 <= LL)
                v = *(const float4*)(g_vt + ((size_t)bh * HDD + row) * LL + kb + c4);
            uint32_t* d = &Vs[row * 68 + c4];
            d[0] = f2tf32(v.x); d[1] = f2tf32(v.y); d[2] = f2tf32(v.z); d[3] = f2tf32(v.w);
        }
        __syncthreads();

        // S = Q K^T  (per-warp 16 x 64)
        float s[8][4];
        #pragma unroll
        for (int nt = 0; nt < 8; nt++)
            #pragma unroll
            for (int i = 0; i < 4; i++) s[nt][i] = 0.f;
        #pragma unroll
        for (int kt = 0; kt < 8; kt++) {
            #pragma unroll
            for (int nt = 0; nt < 8; nt++) {
                uint32_t bf[2];
                bf[0] = Ks[(nt * 8 + g) * 68 + kt * 8 + tg];
                bf[1] = Ks[(nt * 8 + g) * 68 + kt * 8 + tg + 4];
                mma_tf32(s[nt], qf[kt], bf);
            }
        }

        // scale + mask + online softmax
        float mx1 = -1e30f, mx2 = -1e30f;
        #pragma unroll
        for (int nt = 0; nt < 8; nt++) {
            int col = kb + nt * 8 + tg * 2;
            #pragma unroll
            for (int i = 0; i < 4; i++) s[nt][i] *= 0.125f;
            if (col >= LL)     { s[nt][0] = -1e30f; s[nt][2] = -1e30f; }
            if (col + 1 >= LL) { s[nt][1] = -1e30f; s[nt][3] = -1e30f; }
            mx1 = fmaxf(mx1, fmaxf(s[nt][0], s[nt][1]));
            mx2 = fmaxf(mx2, fmaxf(s[nt][2], s[nt][3]));
        }
        #pragma unroll
        for (int o = 1; o <= 2; o <<= 1) {
            mx1 = fmaxf(mx1, __shfl_xor_sync(0xffffffffu, mx1, o));
            mx2 = fmaxf(mx2, __shfl_xor_sync(0xffffffffu, mx2, o));
        }
        const float nm1 = fmaxf(m1, mx1), nm2 = fmaxf(m2, mx2);
        const float f1 = __expf(m1 - nm1), f2 = __expf(m2 - nm2);
        float sum1 = 0.f, sum2 = 0.f;
        #pragma unroll
        for (int nt = 0; nt < 8; nt++) {
            s[nt][0] = __expf(s[nt][0] - nm1); sum1 += s[nt][0];
            s[nt][1] = __expf(s[nt][1] - nm1); sum1 += s[nt][1];
            s[nt][2] = __expf(s[nt][2] - nm2); sum2 += s[nt][2];
            s[nt][3] = __expf(s[nt][3] - nm2); sum2 += s[nt][3];
        }
        #pragma unroll
        for (int o = 1; o <= 2; o <<= 1) {
            sum1 += __shfl_xor_sync(0xffffffffu, sum1, o);
            sum2 += __shfl_xor_sync(0xffffffffu, sum2, o);
        }
        l1 = l1 * f1 + sum1; m1 = nm1;
        l2 = l2 * f2 + sum2; m2 = nm2;
        #pragma unroll
        for (int nt = 0; nt < 8; nt++) {
            oacc[nt][0] *= f1; oacc[nt][1] *= f1;
            oacc[nt][2] *= f2; oacc[nt][3] *= f2;
        }

        // convert P to tf32
        uint32_t pu[8][4];
        #pragma unroll
        for (int nt = 0; nt < 8; nt++)
            #pragma unroll
            for (int i = 0; i < 4; i++) pu[nt][i] = f2tf32(s[nt][i]);

        // P * V : C-fragment -> A-fragment via shuffles
        const int src_a = g * 4 + (tg >> 1);
        const int src_b = src_a + 2;
        const int sel = tg & 1;
        #pragma unroll
        for (int kt = 0; kt < 8; kt++) {
            uint32_t x0 = __shfl_sync(0xffffffffu, pu[kt][0], src_a);
            uint32_t x1 = __shfl_sync(0xffffffffu, pu[kt][1], src_a);
            uint32_t x2 = __shfl_sync(0xffffffffu, pu[kt][2], src_a);
            uint32_t x3 = __shfl_sync(0xffffffffu, pu[kt][3], src_a);
            uint32_t y0 = __shfl_sync(0xffffffffu, pu[kt][0], src_b);
            uint32_t y1 = __shfl_sync(0xffffffffu, pu[kt][1], src_b);
            uint32_t y2 = __shfl_sync(0xffffffffu, pu[kt][2], src_b);
            uint32_t y3 = __shfl_sync(0xffffffffu, pu[kt][3], src_b);
            uint32_t af[4];
            af[0] = sel ? x1 : x0;
            af[1] = sel ? x3 : x2;
            af[2] = sel ? y1 : y0;
            af[3] = sel ? y3 : y2;
            #pragma unroll
            for (int nt = 0; nt < 8; nt++) {
                uint32_t bf[2];
                bf[0] = Vs[(nt * 8 + g) * 68 + kt * 8 + tg];
                bf[1] = Vs[(nt * 8 + g) * 68 + kt * 8 + tg + 4];
                mma_tf32(oacc[nt], af, bf);
            }
        }
    }

    // epilogue: normalize and store to g_o [b,t, h*64+hd]
    const float inv1 = 1.f / l1, inv2 = 1.f / l2;
    float* O1 = g_o + ((size_t)(b * NNq) + m0 + wb + g) * DD + h * HDD;
    float* O2 = O1 + 8 * DD;
    #pragma unroll
    for (int nt = 0; nt < 8; nt++) {
        int c = nt * 8 + tg * 2;
        O1[c]     = oacc[nt][0] * inv1;
        O1[c + 1] = oacc[nt][1] * inv1;
        O2[c]     = oacc[nt][2] * inv2;
        O2[c + 1] = oacc[nt][3] * inv2;
    }
}

// ---------------- LayerNorm (one block per token; out -> g_h) ----------------
template<int XSEL>
__global__ __launch_bounds__(256)
void ln_kernel(const float* __restrict__ xarg, const float* __restrict__ gw,
               const float* __restrict__ bw)
{
    __shared__ float red[2][8];
    __shared__ float s_mu, s_rstd;
    const float* x = buf_ptr<XSEL>(xarg);
    const int row = blockIdx.x;
    const float* xr = x + (size_t)row * DD;
    float* orow = g_h + (size_t)row * DD;
    const int tid = threadIdx.x;

    float lv[3];
    float s = 0.f, s2 = 0.f;
    #pragma unroll
    for (int i = 0; i < 3; i++) {
        float v = xr[tid + i * 256];
        lv[i] = v; s += v; s2 += v * v;
    }
    #pragma unroll
    for (int o = 16; o; o >>= 1) {
        s  += __shfl_xor_sync(0xffffffffu, s,  o);
        s2 += __shfl_xor_sync(0xffffffffu, s2, o);
    }
    if ((tid & 31) == 0) { red[0][tid >> 5] = s; red[1][tid >> 5] = s2; }
    __syncthreads();
    if (tid == 0) {
        float ts = 0.f, ts2 = 0.f;
        #pragma unroll
        for (int i = 0; i < 8; i++) { ts += red[0][i]; ts2 += red[1][i]; }
        float mu = ts * (1.f / 768.f);
        float var = ts2 * (1.f / 768.f) - mu * mu;
        s_mu = mu; s_rstd = rsqrtf(var + 1e-5f);
    }
    __syncthreads();
    const float mu = s_mu, rstd = s_rstd;
    #pragma unroll
    for (int i = 0; i < 3; i++) {
        int c = tid + i * 256;
        orow[c] = (lv[i] - mu) * rstd * gw[c] + bw[c];
    }
}

// ---------------- prompt scatter: prompt[B,2,P,H,HD] -> g_k / g_vt ----------------
__global__ __launch_bounds__(256)
void prompt_copy(const float* __restrict__ pr)
{
    int idx = blockIdx.x * 256 + threadIdx.x;
    if (idx >= BB * 2 * PP * HH * HDD) return;
    float v = pr[idx];
    int hd = idx & 63; int t = idx >> 6;
    int h = t % HH;    t /= HH;
    int p = t % PP;    t /= PP;
    int kv = t & 1;    int b = t >> 1;
    int bh = b * HH + h;
    if (kv == 0) g_k [((size_t)bh * LL + p) * HDD + hd] = v;
    else         g_vt[((size_t)bh * HDD + hd) * LL + p] = v;
}

// ---------------- launcher (kernel launches ONLY) ----------------
extern "C" void kernel_launch(void* const* d_in, const int* in_sizes, int n_in,
                              void* d_out, int out_size)
{
    const float* x      = (const float*)d_in[0];
    const float* prompt = (const float*)d_in[1];
    const float* qkv_w  = (const float*)d_in[2];
    const float* qkv_b  = (const float*)d_in[3];
    const float* out_w  = (const float*)d_in[4];
    const float* out_b  = (const float*)d_in[5];
    const float* ln1_g  = (const float*)d_in[6];
    const float* ln1_b  = (const float*)d_in[7];
    const float* ln2_g  = (const float*)d_in[8];
    const float* ln2_b  = (const float*)d_in[9];
    const float* fc1_w  = (const float*)d_in[10];
    const float* fc1_b  = (const float*)d_in[11];
    const float* fc2_w  = (const float*)d_in[12];
    const float* fc2_b  = (const float*)d_in[13];
    float* outp = (float*)d_out;

    // 1. prompt scatter into K / V^T caches
    prompt_copy<<<(BB * 2 * PP * HH * HDD + 255) / 256, 256>>>(prompt);
    // 2. LN1: x -> g_h
    ln_kernel<0><<<MTOK, 256>>>(x, ln1_g, ln1_b);
    // 3. QKV GEMM + scatter into g_q / g_k / g_vt
    gemm_nt<128, 0, 1, 0, 0><<<dim3(18, 128), 256>>>(
        nullptr, DD, qkv_w, DD, 3 * DD, DD, qkv_b, nullptr, nullptr);
    // 4. fused flash attention -> g_o
    flash_kernel<<<dim3(8, BHh), 256>>>();
    // 5. out-proj + bias + residual(x) -> g_x1
    gemm_nt<128, 3, 2, 0, 3><<<dim3(6, 128), 256>>>(
        nullptr, DD, out_w, DD, DD, DD, out_b, x, nullptr);
    // 6. LN2: g_x1 -> g_h
    ln_kernel<3><<<MTOK, 256>>>(nullptr, ln2_g, ln2_b);
    // 7. FC1 + bias + QuickGELU -> g_m
    gemm_nt<128, 4, 1, 0, 4><<<dim3(24, 128), 256>>>(
        nullptr, DD, fc1_w, DD, FFF, DD, fc1_b, nullptr, nullptr);
    // 8. FC2 + bias + residual(g_x1) -> d_out
    gemm_nt<128, 3, 4, 3, 0><<<dim3(6, 128), 256>>>(
        nullptr, FFF, fc2_w, FFF, DD, FFF, fc2_b, nullptr, outp);
}